// round 7
// baseline (speedup 1.0000x reference)
#include <cuda_runtime.h>
#include <cuda_bf16.h>
#include <math.h>
#include <stdint.h>

#define NMAX 100000
#define EMAX 1700000
#define DMAX 64
#define SCAN_CHUNK 512

// ---------------- scratch (device globals; no allocation allowed) ----------
__device__ int   g_is64;
__device__ int   g_cnt[NMAX];
__device__ int   g_off[NMAX + 1];
__device__ int   g_part[1024];
__device__ int   g_esrc[EMAX];
__device__ float g_e[EMAX];
__device__ __align__(16) float g_h[(size_t)NMAX * DMAX];
__device__ __align__(16) float g_bufA[(size_t)NMAX * DMAX];
__device__ __align__(16) float g_bufB[(size_t)NMAX * DMAX];
__device__ float g_as[NMAX];
__device__ float g_ad[NMAX];

// ---------------- dtype detection ----------------
__global__ void detect_kernel(const unsigned int* __restrict__ w) {
    if (threadIdx.x != 0 || blockIdx.x != 0) return;
    int ok64 = 1;
#pragma unroll
    for (int i = 1; i < 128; i += 2) ok64 &= (w[i] == 0u);
    g_is64 = ok64;
}

__device__ __forceinline__ int load_idx(const void* eiv, long long pos) {
    if (g_is64) return (int)((const long long*)eiv)[pos];
    return ((const int*)eiv)[pos];
}

__device__ __forceinline__ int clampN(int v, int N) {
    return (v < 0) ? 0 : (v >= N ? N - 1 : v);
}

// ---------------- CSR build ----------------
__global__ void zero_cnt_kernel(int N) {
    int i = blockIdx.x * blockDim.x + threadIdx.x;
    if (i < N) g_cnt[i] = 0;
}

__global__ void hist_kernel(const void* __restrict__ eiv, int E, int Etot, int N) {
    int i = blockIdx.x * blockDim.x + threadIdx.x;
    if (i >= Etot) return;
    int d = (i < E) ? clampN(load_idx(eiv, (long long)E + i), N) : (i - E);
    atomicAdd(&g_cnt[d], 1);
}

__global__ void scan_reduce_kernel(int N) {
    __shared__ int sh[256];
    int b = blockIdx.x, t = threadIdx.x;
    int i0 = b * SCAN_CHUNK + t * 2;
    int s = 0;
    if (i0     < N) s += g_cnt[i0];
    if (i0 + 1 < N) s += g_cnt[i0 + 1];
    sh[t] = s;
    __syncthreads();
#pragma unroll
    for (int o = 128; o; o >>= 1) {
        if (t < o) sh[t] += sh[t + o];
        __syncthreads();
    }
    if (t == 0) g_part[b] = sh[0];
}

__global__ void scan_partials_kernel(int B, int N) {
    __shared__ int sh[1024];
    int t = threadIdx.x;
    int v = (t < B) ? g_part[t] : 0;
    sh[t] = v;
    __syncthreads();
#pragma unroll
    for (int o = 1; o < 1024; o <<= 1) {
        int u = (t >= o) ? sh[t - o] : 0;
        __syncthreads();
        sh[t] += u;
        __syncthreads();
    }
    if (t < B) g_part[t] = sh[t] - v;
    if (t == 1023) g_off[N] = sh[1023];
}

__global__ void scan_final_kernel(int N) {
    __shared__ int sh[256];
    int b = blockIdx.x, t = threadIdx.x;
    int i0 = b * SCAN_CHUNK + t * 2;
    int c0 = (i0     < N) ? g_cnt[i0]     : 0;
    int c1 = (i0 + 1 < N) ? g_cnt[i0 + 1] : 0;
    int s = c0 + c1;
    sh[t] = s;
    __syncthreads();
#pragma unroll
    for (int o = 1; o < 256; o <<= 1) {
        int u = (t >= o) ? sh[t - o] : 0;
        __syncthreads();
        sh[t] += u;
        __syncthreads();
    }
    int base = g_part[b] + sh[t] - s;
    if (i0 < N)     { g_off[i0]     = base;      g_cnt[i0]     = base; }
    if (i0 + 1 < N) { g_off[i0 + 1] = base + c0; g_cnt[i0 + 1] = base + c0; }
}

__global__ void scatter_kernel(const void* __restrict__ eiv, int E, int Etot, int N) {
    int i = blockIdx.x * blockDim.x + threadIdx.x;
    if (i >= Etot) return;
    int s, d;
    if (i < E) {
        s = clampN(load_idx(eiv, i), N);
        d = clampN(load_idx(eiv, (long long)E + i), N);
    } else {
        s = d = i - E;
    }
    int p = atomicAdd(&g_cnt[d], 1);
    if (p >= 0 && p < EMAX) g_esrc[p] = s;
}

// ============================================================================
// Layer-0 GEMM via warp-level HMMA (mma.sync m16n8k16 bf16, fp32 accum)
// 3-term bf16 split: acc = Ahi*Bhi + Ahi*Blo + Alo*Bhi  (error ~2^-18)
// CTA: 256 threads = 8 warps; tile 128 rows x 64 cols; K = 256 in 16 steps.
// ============================================================================
#define APK 132                         // A row stride in words (conflict-free: banks 4g+c)
#define OFF_APHI 0                      // 128 * 132 * 4 = 67584 B
#define OFF_APLO 67584
#define OFF_BFRAG 135168                // 16 steps * 8 nfrag * 32 lanes * 16 B = 65536
#define DYN_BYTES (135168 + 65536)      // 200704 B

__device__ __forceinline__ uint32_t pack_bf2(float a, float b) {
    __nv_bfloat162 v = __floats2bfloat162_rn(a, b);
    return *reinterpret_cast<uint32_t*>(&v);
}

__device__ __forceinline__ void mma_bf16(float* d,
    uint32_t a0, uint32_t a1, uint32_t a2, uint32_t a3, uint32_t b0, uint32_t b1) {
    asm volatile(
        "mma.sync.aligned.m16n8k16.row.col.f32.bf16.bf16.f32 "
        "{%0,%1,%2,%3}, {%4,%5,%6,%7}, {%8,%9}, {%0,%1,%2,%3};"
        : "+f"(d[0]), "+f"(d[1]), "+f"(d[2]), "+f"(d[3])
        : "r"(a0), "r"(a1), "r"(a2), "r"(a3), "r"(b0), "r"(b1));
}

__global__ __launch_bounds__(256, 1)
void gemm0_hmma_kernel(const float* __restrict__ X, const float* __restrict__ W,
                       const float* __restrict__ a_s, const float* __restrict__ a_d, int N)
{
    extern __shared__ __align__(16) char sm[];
    uint32_t* Aphi  = reinterpret_cast<uint32_t*>(sm + OFF_APHI);
    uint32_t* Aplo  = reinterpret_cast<uint32_t*>(sm + OFF_APLO);
    uint4*    Bfrag = reinterpret_cast<uint4*>(sm + OFF_BFRAG);
    __shared__ float as_s[64], ad_s[64];

    int tid = threadIdx.x, wid = tid >> 5, lane = tid & 31;
    int row0 = blockIdx.x * 128;
    if (tid < 64) { as_s[tid] = a_s[tid]; ad_s[tid] = a_d[tid]; }

    // ---- stage A: X rows -> packed bf16x2 k-pairs, hi/lo split ----
    const float4* X4 = reinterpret_cast<const float4*>(X);
    for (int idx = tid; idx < 128 * 64; idx += 256) {
        int row = idx >> 6, q = idx & 63;            // q-th float4: cols 4q..4q+3
        int gn = row0 + row;
        float4 v = make_float4(0.f, 0.f, 0.f, 0.f);
        if (gn < N) v = X4[(size_t)gn * 64 + q];
        float hx = __bfloat162float(__float2bfloat16(v.x));
        float hy = __bfloat162float(__float2bfloat16(v.y));
        float hz = __bfloat162float(__float2bfloat16(v.z));
        float hw = __bfloat162float(__float2bfloat16(v.w));
        *reinterpret_cast<uint2*>(&Aphi[row * APK + 2 * q]) =
            make_uint2(pack_bf2(hx, hy), pack_bf2(hz, hw));
        *reinterpret_cast<uint2*>(&Aplo[row * APK + 2 * q]) =
            make_uint2(pack_bf2(v.x - hx, v.y - hy), pack_bf2(v.z - hz, v.w - hw));
    }

    // ---- stage B: ready-to-load mma fragments (hi pair, lo pair per lane) ----
    for (int idx = tid; idx < 4096; idx += 256) {
        int l = idx & 31, nf = (idx >> 5) & 7, s = idx >> 8;
        int c = l & 3, n = (l >> 2) + nf * 8;
        int k0 = s * 16 + c * 2;
        float w0 = W[(size_t)k0 * 64 + n];
        float w1 = W[(size_t)(k0 + 1) * 64 + n];
        float w2 = W[(size_t)(k0 + 8) * 64 + n];
        float w3 = W[(size_t)(k0 + 9) * 64 + n];
        float h0 = __bfloat162float(__float2bfloat16(w0));
        float h1 = __bfloat162float(__float2bfloat16(w1));
        float h2 = __bfloat162float(__float2bfloat16(w2));
        float h3 = __bfloat162float(__float2bfloat16(w3));
        Bfrag[idx] = make_uint4(pack_bf2(h0, h1), pack_bf2(h2, h3),
                                pack_bf2(w0 - h0, w1 - h1), pack_bf2(w2 - h2, w3 - h3));
    }
    __syncthreads();

    // ---- mainloop ----
    float d[8][4] = {};
    int g = lane >> 2, c = lane & 3;
    int abase  = (wid * 16 + g) * APK;
    int abase8 = abase + 8 * APK;
#pragma unroll
    for (int s = 0; s < 16; s++) {
        int kp = s * 8 + c;
        uint32_t aH0 = Aphi[abase  + kp];
        uint32_t aH1 = Aphi[abase8 + kp];
        uint32_t aH2 = Aphi[abase  + kp + 4];
        uint32_t aH3 = Aphi[abase8 + kp + 4];
        uint32_t aL0 = Aplo[abase  + kp];
        uint32_t aL1 = Aplo[abase8 + kp];
        uint32_t aL2 = Aplo[abase  + kp + 4];
        uint32_t aL3 = Aplo[abase8 + kp + 4];
#pragma unroll
        for (int nf = 0; nf < 8; nf++) {
            uint4 b = Bfrag[(s * 8 + nf) * 32 + lane];
            mma_bf16(d[nf], aH0, aH1, aH2, aH3, b.x, b.y);   // Ahi*Bhi
            mma_bf16(d[nf], aH0, aH1, aH2, aH3, b.z, b.w);   // Ahi*Blo
            mma_bf16(d[nf], aL0, aL1, aL2, aL3, b.x, b.y);   // Alo*Bhi
        }
    }

    // ---- epilogue: store h + fused attention dots ----
    int r0g = row0 + wid * 16 + g;
    int r1g = r0g + 8;
    float sd0 = 0.f, dd0 = 0.f, sd1 = 0.f, dd1 = 0.f;
#pragma unroll
    for (int nf = 0; nf < 8; nf++) {
        int n = nf * 8 + 2 * c;
        if (r0g < N) *reinterpret_cast<float2*>(&g_h[(size_t)r0g * 64 + n]) =
            make_float2(d[nf][0], d[nf][1]);
        if (r1g < N) *reinterpret_cast<float2*>(&g_h[(size_t)r1g * 64 + n]) =
            make_float2(d[nf][2], d[nf][3]);
        sd0 += d[nf][0] * as_s[n] + d[nf][1] * as_s[n + 1];
        dd0 += d[nf][0] * ad_s[n] + d[nf][1] * ad_s[n + 1];
        sd1 += d[nf][2] * as_s[n] + d[nf][3] * as_s[n + 1];
        dd1 += d[nf][2] * ad_s[n] + d[nf][3] * ad_s[n + 1];
    }
#pragma unroll
    for (int o = 1; o <= 2; o <<= 1) {
        sd0 += __shfl_xor_sync(0xffffffffu, sd0, o);
        dd0 += __shfl_xor_sync(0xffffffffu, dd0, o);
        sd1 += __shfl_xor_sync(0xffffffffu, sd1, o);
        dd1 += __shfl_xor_sync(0xffffffffu, dd1, o);
    }
    if (c == 0) {
        if (r0g < N) { g_as[r0g] = sd0; g_ad[r0g] = dd0; }
        if (r1g < N) { g_as[r1g] = sd1; g_ad[r1g] = dd1; }
    }
}

// ---------------- SIMT GEMM (layers 1,2) + fused attention dots ------------
__global__ __launch_bounds__(256) void gemm_kernel(
    int sel_in, const float* __restrict__ W,
    const float* __restrict__ a_s, const float* __restrict__ a_d,
    int N, int F, int D, int relu_in)
{
    const float* X = (sel_in == 1 ? (const float*)g_bufA : (const float*)g_bufB);
    __shared__ __align__(16) float xs[16][132];
    __shared__ __align__(16) float ws[16][64];
    __shared__ float as_s[64], ad_s[64];
    int tid  = threadIdx.x;
    int row0 = blockIdx.x * 128;
    int tr = tid >> 4, tc = tid & 15;
    float acc[8][4] = {};
    int f0 = tid * 2;
    int lrow0 = f0 >> 2, lq0 = f0 & 3;
    int lrow1 = (f0 + 1) >> 2, lq1 = (f0 + 1) & 3;
    int wcol = tid & 63, wk0 = (tid >> 6) << 2;

    if (tid < 64) {
        as_s[tid] = (tid < D) ? a_s[tid] : 0.f;
        ad_s[tid] = (tid < D) ? a_d[tid] : 0.f;
    }

    for (int k0 = 0; k0 < F; k0 += 16) {
        float4 xv0 = make_float4(0.f,0.f,0.f,0.f), xv1 = make_float4(0.f,0.f,0.f,0.f);
        int gn0 = row0 + lrow0, gn1 = row0 + lrow1;
        if (gn0 < N) xv0 = reinterpret_cast<const float4*>(X + (size_t)gn0 * F + k0)[lq0];
        if (gn1 < N) xv1 = reinterpret_cast<const float4*>(X + (size_t)gn1 * F + k0)[lq1];
        if (relu_in) {
            xv0.x = fmaxf(xv0.x, 0.f); xv0.y = fmaxf(xv0.y, 0.f);
            xv0.z = fmaxf(xv0.z, 0.f); xv0.w = fmaxf(xv0.w, 0.f);
            xv1.x = fmaxf(xv1.x, 0.f); xv1.y = fmaxf(xv1.y, 0.f);
            xv1.z = fmaxf(xv1.z, 0.f); xv1.w = fmaxf(xv1.w, 0.f);
        }
        xs[lq0 * 4 + 0][lrow0] = xv0.x;
        xs[lq0 * 4 + 1][lrow0] = xv0.y;
        xs[lq0 * 4 + 2][lrow0] = xv0.z;
        xs[lq0 * 4 + 3][lrow0] = xv0.w;
        xs[lq1 * 4 + 0][lrow1] = xv1.x;
        xs[lq1 * 4 + 1][lrow1] = xv1.y;
        xs[lq1 * 4 + 2][lrow1] = xv1.z;
        xs[lq1 * 4 + 3][lrow1] = xv1.w;
#pragma unroll
        for (int j = 0; j < 4; j++) {
            int k = wk0 + j;
            ws[k][wcol] = (wcol < D) ? W[(size_t)(k0 + k) * D + wcol] : 0.f;
        }
        __syncthreads();
#pragma unroll
        for (int k = 0; k < 16; k++) {
            float4 a04 = *(const float4*)&xs[k][tr * 8];
            float4 a48 = *(const float4*)&xs[k][tr * 8 + 4];
            float4 b   = *(const float4*)&ws[k][tc * 4];
            acc[0][0] += a04.x * b.x; acc[0][1] += a04.x * b.y; acc[0][2] += a04.x * b.z; acc[0][3] += a04.x * b.w;
            acc[1][0] += a04.y * b.x; acc[1][1] += a04.y * b.y; acc[1][2] += a04.y * b.z; acc[1][3] += a04.y * b.w;
            acc[2][0] += a04.z * b.x; acc[2][1] += a04.z * b.y; acc[2][2] += a04.z * b.z; acc[2][3] += a04.z * b.w;
            acc[3][0] += a04.w * b.x; acc[3][1] += a04.w * b.y; acc[3][2] += a04.w * b.z; acc[3][3] += a04.w * b.w;
            acc[4][0] += a48.x * b.x; acc[4][1] += a48.x * b.y; acc[4][2] += a48.x * b.z; acc[4][3] += a48.x * b.w;
            acc[5][0] += a48.y * b.x; acc[5][1] += a48.y * b.y; acc[5][2] += a48.y * b.z; acc[5][3] += a48.y * b.w;
            acc[6][0] += a48.z * b.x; acc[6][1] += a48.z * b.y; acc[6][2] += a48.z * b.z; acc[6][3] += a48.z * b.w;
            acc[7][0] += a48.w * b.x; acc[7][1] += a48.w * b.y; acc[7][2] += a48.w * b.z; acc[7][3] += a48.w * b.w;
        }
        __syncthreads();
    }

    float sdot[8] = {}, ddot[8] = {};
    int c0 = tc * 4;
#pragma unroll
    for (int i = 0; i < 8; i++) {
        int n = row0 + tr * 8 + i;
        bool ok = (n < N);
#pragma unroll
        for (int j = 0; j < 4; j++) {
            int c = c0 + j;
            if (ok && c < D) g_h[(size_t)n * D + c] = acc[i][j];
            float w = (c < D) ? acc[i][j] : 0.f;
            sdot[i] += w * as_s[c];
            ddot[i] += w * ad_s[c];
        }
    }
#pragma unroll
    for (int o = 8; o; o >>= 1) {
#pragma unroll
        for (int i = 0; i < 8; i++) {
            sdot[i] += __shfl_xor_sync(0xffffffffu, sdot[i], o);
            ddot[i] += __shfl_xor_sync(0xffffffffu, ddot[i], o);
        }
    }
    if (tc == 0) {
#pragma unroll
        for (int i = 0; i < 8; i++) {
            int n = row0 + tr * 8 + i;
            if (n < N) { g_as[n] = sdot[i]; g_ad[n] = ddot[i]; }
        }
    }
}

// ---------------- fused segment softmax + aggregation (warp per dst) -------
__global__ void agg_kernel(float* OUText, int sel_out, int N, int D)
{
    float* OUT = (sel_out == 0) ? OUText : (sel_out == 1 ? g_bufA : g_bufB);
    int warp = (blockIdx.x * blockDim.x + threadIdx.x) >> 5;
    int lane = threadIdx.x & 31;
    int nw = (gridDim.x * blockDim.x) >> 5;
    const float2* H2 = reinterpret_cast<const float2*>(g_h);
    int rowst = D >> 1;

    for (int n = warp; n < N; n += nw) {
        int beg = g_off[n], end = g_off[n + 1];
        float adn = g_ad[n];

        float m = -INFINITY;
        for (int p = beg + lane; p < end; p += 32) {
            float v = g_as[g_esrc[p]] + adn;
            v = (v > 0.f) ? v : 0.2f * v;
            g_e[p] = v;
            m = fmaxf(m, v);
        }
#pragma unroll
        for (int o = 16; o; o >>= 1) m = fmaxf(m, __shfl_xor_sync(0xffffffffu, m, o));

        float sum = 0.f;
        for (int p = beg + lane; p < end; p += 32) {
            float ex = __expf(g_e[p] - m);
            g_e[p] = ex;
            sum += ex;
        }
#pragma unroll
        for (int o = 16; o; o >>= 1) sum += __shfl_xor_sync(0xffffffffu, sum, o);
        float inv = 1.f / (sum + 1e-16f);

        int c0 = lane * 2;
        bool act = (c0 < D);
        float2 acc = make_float2(0.f, 0.f);
        int p = beg;
        for (; p + 1 < end; p += 2) {
            float a0 = g_e[p] * inv;
            float a1 = g_e[p + 1] * inv;
            int s0 = g_esrc[p];
            int s1 = g_esrc[p + 1];
            if (act) {
                float2 h0 = H2[(size_t)s0 * rowst + lane];
                float2 h1 = H2[(size_t)s1 * rowst + lane];
                acc.x += a0 * h0.x + a1 * h1.x;
                acc.y += a0 * h0.y + a1 * h1.y;
            }
        }
        if (p < end) {
            float a0 = g_e[p] * inv;
            int s0 = g_esrc[p];
            if (act) {
                float2 h0 = H2[(size_t)s0 * rowst + lane];
                acc.x += a0 * h0.x;
                acc.y += a0 * h0.y;
            }
        }
        if (act) {
            OUT[(size_t)n * D + c0]     = acc.x;
            OUT[(size_t)n * D + c0 + 1] = acc.y;
        }
    }
}

// ---------------- launch ----------------
extern "C" void kernel_launch(void* const* d_in, const int* in_sizes, int n_in,
                              void* d_out, int out_size)
{
    const float* x     = (const float*)d_in[0];
    const void*  ei    = d_in[1];
    const float* W0    = (const float*)d_in[2];
    const float* asrc0 = (const float*)d_in[3];
    const float* adst0 = (const float*)d_in[4];
    const float* W1    = (const float*)d_in[5];
    const float* asrc1 = (const float*)d_in[6];
    const float* adst1 = (const float*)d_in[7];
    const float* W2    = (const float*)d_in[8];
    const float* asrc2 = (const float*)d_in[9];
    const float* adst2 = (const float*)d_in[10];

    int H    = in_sizes[3];            // 64
    int C    = in_sizes[9];            // 40
    int Fin  = in_sizes[2] / H;        // 256
    int N    = in_sizes[0] / Fin;      // 100000
    int E    = in_sizes[1] / 2;        // 1600000
    int Etot = E + N;
    int SB   = (N + SCAN_CHUNK - 1) / SCAN_CHUNK;

    static cudaStream_t s2 = nullptr;
    static cudaEvent_t ev_fork = nullptr, ev_csr = nullptr;
    if (!s2) {
        cudaStreamCreateWithFlags(&s2, cudaStreamNonBlocking);
        cudaEventCreateWithFlags(&ev_fork, cudaEventDisableTiming);
        cudaEventCreateWithFlags(&ev_csr, cudaEventDisableTiming);
        cudaFuncSetAttribute(gemm0_hmma_kernel,
                             cudaFuncAttributeMaxDynamicSharedMemorySize, DYN_BYTES);
    }

    // fork: CSR build on s2, concurrent with gemm0 on the main stream
    cudaEventRecord(ev_fork, 0);
    cudaStreamWaitEvent(s2, ev_fork, 0);

    detect_kernel<<<1, 32, 0, s2>>>((const unsigned int*)ei);
    zero_cnt_kernel<<<(N + 255) / 256, 256, 0, s2>>>(N);
    hist_kernel<<<(Etot + 255) / 256, 256, 0, s2>>>(ei, E, Etot, N);
    scan_reduce_kernel<<<SB, 256, 0, s2>>>(N);
    scan_partials_kernel<<<1, 1024, 0, s2>>>(SB, N);
    scan_final_kernel<<<SB, 256, 0, s2>>>(N);
    scatter_kernel<<<(Etot + 255) / 256, 256, 0, s2>>>(ei, E, Etot, N);
    cudaEventRecord(ev_csr, s2);

    int gemm_blocks = (N + 127) / 128;
    int wg_blocks   = (N + 7) / 8;

    // layer 0: HMMA bf16-split GEMM (concurrent with CSR build)
    gemm0_hmma_kernel<<<gemm_blocks, 256, DYN_BYTES>>>(x, W0, asrc0, adst0, N);

    cudaStreamWaitEvent(0, ev_csr, 0);
    agg_kernel<<<wg_blocks, 256>>>(nullptr, 1, N, H);

    gemm_kernel<<<gemm_blocks, 256>>>(1, W1, asrc1, adst1, N, H, H, 1);
    agg_kernel<<<wg_blocks, 256>>>(nullptr, 2, N, H);

    gemm_kernel<<<gemm_blocks, 256>>>(2, W2, asrc2, adst2, N, H, C, 1);
    agg_kernel<<<wg_blocks, 256>>>((float*)d_out, 0, N, C);
}